// round 13
// baseline (speedup 1.0000x reference)
#include <cuda_runtime.h>
#include <cstdint>

#define BN 4096
#define CN 80
#define ERRN 4

// ---------------- scratch (static device arrays; no allocation) ----------------
__device__ __align__(16) unsigned char g_lid8[BN];
__device__ uint32_t g_best32[2][BN][256];   // per-virtual-thread best VALUES (8 MB)

// ---------------- threefry2x32 (exact JAX semantics) ----------------
__host__ __device__ __forceinline__ uint32_t tf_rotl(uint32_t v, int r) {
    return (v << r) | (v >> (32 - r));
}

// full version (host key derivation)
__host__ __device__ __forceinline__ void threefry2x32(uint32_t k0, uint32_t k1,
                                                      uint32_t c0, uint32_t c1,
                                                      uint32_t& o0, uint32_t& o1) {
    uint32_t ks0 = k0, ks1 = k1, ks2 = k0 ^ k1 ^ 0x1BD11BDAu;
    uint32_t x0 = c0 + ks0;
    uint32_t x1 = c1 + ks1;
#define TF_RND(r) { x0 += x1; x1 = tf_rotl(x1, r); x1 ^= x0; }
    TF_RND(13) TF_RND(15) TF_RND(26) TF_RND(6)
    x0 += ks1; x1 += ks2 + 1u;
    TF_RND(17) TF_RND(29) TF_RND(16) TF_RND(24)
    x0 += ks2; x1 += ks0 + 2u;
    TF_RND(13) TF_RND(15) TF_RND(26) TF_RND(6)
    x0 += ks0; x1 += ks1 + 3u;
    TF_RND(17) TF_RND(29) TF_RND(16) TF_RND(24)
    x0 += ks1; x1 += ks2 + 4u;
    TF_RND(13) TF_RND(15) TF_RND(26) TF_RND(6)
    x0 += ks2; x1 += ks0 + 5u;
#undef TF_RND
    o0 = x0; o1 = x1;
}

// Hot path: x0^x1 of threefry((k0,k1),(0,c1)).
// rotl forced onto the fma pipe: mul.wide.u32 (one IMAD.WIDE) produces
// w = x1 * 2^r; rotl = lo(w) | hi(w) = lo(w) ^ hi(w) (disjoint bits), so
// x1' = lo ^ hi ^ x0 is a single LOP3. Per round: 1 alu + 1 fma + 1 flex add.
// Inline asm prevents ptxas from strength-reducing the mul back to SHF.
__device__ __forceinline__ uint32_t tf_bits(uint32_t k0, uint32_t k1,
                                            uint32_t ks2, uint32_t c1) {
    uint32_t x0 = k0;
    uint32_t x1 = c1 + k1;
#define RND(r) { x0 += x1; \
    unsigned long long w; \
    asm("mul.wide.u32 %0, %1, %2;" : "=l"(w) : "r"(x1), "r"(1u << (r))); \
    x1 = (uint32_t)w ^ (uint32_t)(w >> 32) ^ x0; }
#define GRP_A RND(13) RND(15) RND(26) RND(6)
#define GRP_B RND(17) RND(29) RND(16) RND(24)
    GRP_A
    x0 += k1;  x1 += ks2 + 1u;
    GRP_B
    x0 += ks2; x1 += k0 + 2u;
    GRP_A
    x0 += k0;  x1 += k1 + 3u;
    GRP_B
    x0 += k1;  x1 += ks2 + 4u;
    GRP_A
    x0 += ks2; x1 += k0 + 5u;
#undef GRP_A
#undef GRP_B
#undef RND
    return x0 ^ x1;
}

// ---------------- top-4 helpers ----------------
__device__ __forceinline__ void ins4u(uint32_t* t, uint32_t c) {
    if (c > t[0])      { t[3] = t[2]; t[2] = t[1]; t[1] = t[0]; t[0] = c; }
    else if (c > t[1]) { t[3] = t[2]; t[2] = t[1]; t[1] = c; }
    else if (c > t[2]) { t[3] = t[2]; t[2] = c; }
    else if (c > t[3]) { t[3] = c; }
}

__device__ __forceinline__ void warp_merge4u(uint32_t* top) {
    for (int off = 16; off > 0; off >>= 1) {
        uint32_t o0 = __shfl_xor_sync(0xFFFFFFFFu, top[0], off);
        uint32_t o1 = __shfl_xor_sync(0xFFFFFFFFu, top[1], off);
        uint32_t o2 = __shfl_xor_sync(0xFFFFFFFFu, top[2], off);
        uint32_t o3 = __shfl_xor_sync(0xFFFFFFFFu, top[3], off);
        ins4u(top, o0); ins4u(top, o1); ins4u(top, o2); ins4u(top, o3);
    }
}

__device__ __forceinline__ void ins4(unsigned long long* t, unsigned long long c) {
    if (c > t[0])      { t[3] = t[2]; t[2] = t[1]; t[1] = t[0]; t[0] = c; }
    else if (c > t[1]) { t[3] = t[2]; t[2] = t[1]; t[1] = c; }
    else if (c > t[2]) { t[3] = t[2]; t[2] = c; }
    else if (c > t[3]) { t[3] = c; }
}

__device__ __forceinline__ void warp_merge4(unsigned long long* top) {
    for (int off = 16; off > 0; off >>= 1) {
        unsigned long long o0 = __shfl_xor_sync(0xFFFFFFFFu, top[0], off);
        unsigned long long o1 = __shfl_xor_sync(0xFFFFFFFFu, top[1], off);
        unsigned long long o2 = __shfl_xor_sync(0xFFFFFFFFu, top[2], off);
        unsigned long long o3 = __shfl_xor_sync(0xFFFFFFFFu, top[3], off);
        ins4(top, o0); ins4(top, o1); ins4(top, o2); ins4(top, o3);
    }
}

// ---------------- kernels ----------------
// one warp per row; float4 loads (80 floats = 20 float4). Also zeroes d_out.
__global__ __launch_bounds__(256) void k_labelid(const float* __restrict__ labels,
                                                 float* __restrict__ out,
                                                 int out_size) {
    int warp = (blockIdx.x * blockDim.x + threadIdx.x) >> 5;
    int lane = threadIdx.x & 31;
    if (blockIdx.x == 0 && threadIdx.x < out_size) out[threadIdx.x] = 0.0f;
    if (warp >= BN) return;
    const float4* row = (const float4*)(labels + (size_t)warp * CN);
    unsigned best = 0;
    if (lane < CN / 4) {
        float4 v = row[lane];
        unsigned j = (unsigned)lane * 4u;
        if (v.x > 0.5f) best = j;
        if (v.y > 0.5f) best = j + 1;
        if (v.z > 0.5f) best = j + 2;
        if (v.w > 0.5f) best = j + 3;
    }
    best = __reduce_max_sync(0xFFFFFFFFu, best);
    if (lane == 0) g_lid8[warp] = (unsigned char)best;
}

// PHASE 1, VALUE-ONLY. grid (4096, 4), block 64. Virtual thread
// vt = by*64 + tid owns j in [16*vt, 16*vt+16). Per vt, per key:
//   best = max over s of ((bits>>9)+1) * valid   (0 if none valid)
// No position tracking (merge rescans owner threads exactly).
// No smem, no barriers.
__global__ __launch_bounds__(64) void k_select(uint32_t a0, uint32_t a1,
                                               uint32_t b0, uint32_t b1) {
    const int row = blockIdx.x;
    const int vt = blockIdx.y * 64 + threadIdx.x;   // 0..255
    const uint32_t ksA2 = a0 ^ a1 ^ 0x1BD11BDAu;
    const uint32_t ksB2 = b0 ^ b1 ^ 0x1BD11BDAu;

    const uint32_t mylid = (uint32_t)g_lid8[row];
    const uint32_t rep = mylid * 0x01010101u;
    const uint4 l4 = reinterpret_cast<const uint4*>(g_lid8)[vt];
    uint32_t vw[4];
    vw[0] = __vcmpne4(l4.x, rep) & 0x01010101u;
    vw[1] = __vcmpne4(l4.y, rep) & 0x01010101u;
    vw[2] = __vcmpne4(l4.z, rep) & 0x01010101u;
    vw[3] = __vcmpne4(l4.w, rep) & 0x01010101u;

    const uint32_t cbase = (uint32_t)row * (uint32_t)BN + (uint32_t)vt * 16u;

    uint32_t bestA = 0u, bestB = 0u;
    #pragma unroll 4
    for (int s = 0; s < 16; s++) {
        uint32_t bitsA = tf_bits(a0, a1, ksA2, cbase + (uint32_t)s);
        uint32_t bitsB = tf_bits(b0, b1, ksB2, cbase + (uint32_t)s);
        uint32_t v01 = __byte_perm(vw[s >> 2], 0u, 0x4440u | (unsigned)(s & 3));
        uint32_t cA = (bitsA >> 9) * v01 + v01;   // ((bits>>9)+1)*valid, 1 IMAD
        uint32_t cB = (bitsB >> 9) * v01 + v01;
        bestA = max(bestA, cA);
        bestB = max(bestB, cB);
    }

    g_best32[0][row][vt] = bestA;
    g_best32[1][row][vt] = bestB;
}

__device__ __forceinline__ float warp_sum(float s) {
    for (int off = 16; off > 0; off >>= 1)
        s += __shfl_xor_sync(0xFFFFFFFFu, s, off);
    return s;
}

__device__ __forceinline__ float dist4(float4 a, float4 b) {
    float dx = a.x - b.x, dy = a.y - b.y, dz = a.z - b.z, dw = a.w - b.w;
    float s = dx * dx + dy * dy + dz * dz + dw * dw;
    s = warp_sum(s);
    return sqrtf(fmaxf(s, 0.0f));
}

// FUSED merge + rescan + loss. grid 1024, block 256 = 8 warps;
// warp w -> pair g = blockIdx.x*8+w -> (row = g>>1, dir = g&1).
// Step 1: warp top-4 owner vthreads by (value<<8)|(255-t)  [u32].
// Step 2: exact rescan of the 4 owners (64 evals, 2/lane) with u64 packing
//         ((v+1)<<12)|(4095-j), ties -> lower j. All lanes converge.
// Step 3: distances for this (row,dir): pos + 4 negatives, hinge, reduce.
__global__ __launch_bounds__(256) void k_mergeloss(const float* __restrict__ img,
                                                   const float* __restrict__ txt,
                                                   float* __restrict__ out,
                                                   uint32_t a0, uint32_t a1,
                                                   uint32_t b0, uint32_t b1) {
    const int w = threadIdx.x >> 5;
    const int lane = threadIdx.x & 31;
    const int g = blockIdx.x * 8 + w;
    const int row = g >> 1;
    const int dir = g & 1;

    const uint32_t kk0 = dir ? b0 : a0;
    const uint32_t kk1 = dir ? b1 : a1;
    const uint32_t kks2 = kk0 ^ kk1 ^ 0x1BD11BDAu;
    const uint32_t mylid = (uint32_t)g_lid8[row];

    // step 1: top-4 owner vthreads (value, lower-t wins ties)
    uint32_t top[4] = {0u, 0u, 0u, 0u};
    #pragma unroll
    for (int k = 0; k < 8; k++) {
        int t = lane + 32 * k;
        uint32_t v = g_best32[dir][row][t];   // (bits>>9)+1, or 0
        if (v) ins4u(top, (v << 8) | (uint32_t)(255 - t));
    }
    warp_merge4u(top);   // all lanes: same 4 packed owners

    // step 2: exact rescan, 2 evals per lane
    unsigned long long fin[4] = {0ull, 0ull, 0ull, 0ull};
    #pragma unroll
    for (int k = 0; k < 2; k++) {
        int p = lane + 32 * k;          // 0..63
        int c = p >> 4;                 // candidate 0..3
        int s = p & 15;                 // element within owner thread
        uint32_t tc = top[c];
        if (tc != 0u) {
            int to = 255 - (int)(tc & 0xFFu);   // owner vthread
            int j = to * 16 + s;
            if ((uint32_t)g_lid8[j] != mylid) {
                uint32_t bits = tf_bits(kk0, kk1, kks2,
                                        (uint32_t)row * (uint32_t)BN + (uint32_t)j);
                unsigned long long pv =
                    (((unsigned long long)((bits >> 9) + 1u)) << 12) |
                    (unsigned long long)(BN - 1 - j);
                ins4(fin, pv);
            }
        }
    }
    warp_merge4(fin);   // all lanes: final top-4 (exact)

    // step 3: distances
    const float4* img4 = (const float4*)img;
    const float4* txt4 = (const float4*)txt;

    float4 ai = img4[row * 32 + lane];
    float4 ti = txt4[row * 32 + lane];
    float pos = dist4(ai, ti);

    const float4* nsrc = dir ? img4 : txt4;
    float4 anc = dir ? ti : ai;

    float acc = 0.0f;
    #pragma unroll
    for (int k = 0; k < ERRN; k++) {
        int j = BN - 1 - (int)(fin[k] & 0xFFFull);   // warp-uniform
        float4 bj = nsrc[j * 32 + lane];
        float neg = dist4(anc, bj);
        acc += fmaxf(pos - neg + 1.0f, 0.0f);
    }

    __shared__ float ssum[8];
    if (lane == 0) ssum[w] = acc;
    __syncthreads();
    if (threadIdx.x == 0) {
        float t = 0.0f;
        #pragma unroll
        for (int k = 0; k < 8; k++) t += ssum[k];
        atomicAdd(out, t * (1.0f / (float)(BN * ERRN)));
    }
}

// ---------------- launch ----------------
extern "C" void kernel_launch(void* const* d_in, const int* in_sizes, int n_in,
                              void* d_out, int out_size) {
    const float* img    = (const float*)d_in[0];
    const float* txt    = (const float*)d_in[1];
    const float* labels = (const float*)d_in[2];
    float* out = (float*)d_out;

    // jax.random.key(42) -> (0,42); partitionable foldlike split:
    // key_i = threefry((0,42), (0, i)).
    uint32_t a0, a1, b0, b1;
    threefry2x32(0u, 42u, 0u, 0u, a0, a1);  // ks1 (image->text scores)
    threefry2x32(0u, 42u, 0u, 1u, b0, b1);  // ks2 (text->image scores)

    k_labelid<<<512, 256>>>(labels, out, out_size);
    dim3 gsel(BN, 4);
    k_select<<<gsel, 64>>>(a0, a1, b0, b1);
    k_mergeloss<<<BN / 4, 256>>>(img, txt, out, a0, a1, b0, b1);
}

// round 14
// speedup vs baseline: 1.2069x; 1.2069x over previous
#include <cuda_runtime.h>
#include <cstdint>

#define BN 4096
#define CN 80
#define ERRN 4

// ---------------- scratch (static device arrays; no allocation) ----------------
__device__ __align__(16) unsigned char g_lid8[BN];
__device__ uint32_t g_best32[2][BN][256];   // per-virtual-thread best VALUES (8 MB)

// ---------------- threefry2x32 (exact JAX semantics) ----------------
__host__ __device__ __forceinline__ uint32_t tf_rotl(uint32_t v, int r) {
    return (v << r) | (v >> (32 - r));
}

// full version (host key derivation)
__host__ __device__ __forceinline__ void threefry2x32(uint32_t k0, uint32_t k1,
                                                      uint32_t c0, uint32_t c1,
                                                      uint32_t& o0, uint32_t& o1) {
    uint32_t ks0 = k0, ks1 = k1, ks2 = k0 ^ k1 ^ 0x1BD11BDAu;
    uint32_t x0 = c0 + ks0;
    uint32_t x1 = c1 + ks1;
#define TF_RND(r) { x0 += x1; x1 = tf_rotl(x1, r); x1 ^= x0; }
    TF_RND(13) TF_RND(15) TF_RND(26) TF_RND(6)
    x0 += ks1; x1 += ks2 + 1u;
    TF_RND(17) TF_RND(29) TF_RND(16) TF_RND(24)
    x0 += ks2; x1 += ks0 + 2u;
    TF_RND(13) TF_RND(15) TF_RND(26) TF_RND(6)
    x0 += ks0; x1 += ks1 + 3u;
    TF_RND(17) TF_RND(29) TF_RND(16) TF_RND(24)
    x0 += ks1; x1 += ks2 + 4u;
    TF_RND(13) TF_RND(15) TF_RND(26) TF_RND(6)
    x0 += ks2; x1 += ks0 + 5u;
#undef TF_RND
    o0 = x0; o1 = x1;
}

// Hot path: x0^x1 of threefry((k0,k1),(0,c1)). SHF/LOP3 form — verified
// best instruction selection (IMAD.WIDE form regressed, R13).
__device__ __forceinline__ uint32_t tf_bits(uint32_t k0, uint32_t k1,
                                            uint32_t ks2, uint32_t c1) {
    uint32_t x0 = k0;
    uint32_t x1 = c1 + k1;
#define RND(r) { x0 += x1; x1 = __funnelshift_l(x1, x1, (r)) ^ x0; }
#define GRP_A RND(13) RND(15) RND(26) RND(6)
#define GRP_B RND(17) RND(29) RND(16) RND(24)
    GRP_A
    x0 += k1;  x1 += ks2 + 1u;
    GRP_B
    x0 += ks2; x1 += k0 + 2u;
    GRP_A
    x0 += k0;  x1 += k1 + 3u;
    GRP_B
    x0 += k1;  x1 += ks2 + 4u;
    GRP_A
    x0 += ks2; x1 += k0 + 5u;
#undef GRP_A
#undef GRP_B
#undef RND
    return x0 ^ x1;
}

// ---------------- top-4 helpers ----------------
__device__ __forceinline__ void ins4u(uint32_t* t, uint32_t c) {
    if (c > t[0])      { t[3] = t[2]; t[2] = t[1]; t[1] = t[0]; t[0] = c; }
    else if (c > t[1]) { t[3] = t[2]; t[2] = t[1]; t[1] = c; }
    else if (c > t[2]) { t[3] = t[2]; t[2] = c; }
    else if (c > t[3]) { t[3] = c; }
}

__device__ __forceinline__ void warp_merge4u(uint32_t* top) {
    for (int off = 16; off > 0; off >>= 1) {
        uint32_t o0 = __shfl_xor_sync(0xFFFFFFFFu, top[0], off);
        uint32_t o1 = __shfl_xor_sync(0xFFFFFFFFu, top[1], off);
        uint32_t o2 = __shfl_xor_sync(0xFFFFFFFFu, top[2], off);
        uint32_t o3 = __shfl_xor_sync(0xFFFFFFFFu, top[3], off);
        ins4u(top, o0); ins4u(top, o1); ins4u(top, o2); ins4u(top, o3);
    }
}

__device__ __forceinline__ void ins4(unsigned long long* t, unsigned long long c) {
    if (c > t[0])      { t[3] = t[2]; t[2] = t[1]; t[1] = t[0]; t[0] = c; }
    else if (c > t[1]) { t[3] = t[2]; t[2] = t[1]; t[1] = c; }
    else if (c > t[2]) { t[3] = t[2]; t[2] = c; }
    else if (c > t[3]) { t[3] = c; }
}

__device__ __forceinline__ void warp_merge4(unsigned long long* top) {
    for (int off = 16; off > 0; off >>= 1) {
        unsigned long long o0 = __shfl_xor_sync(0xFFFFFFFFu, top[0], off);
        unsigned long long o1 = __shfl_xor_sync(0xFFFFFFFFu, top[1], off);
        unsigned long long o2 = __shfl_xor_sync(0xFFFFFFFFu, top[2], off);
        unsigned long long o3 = __shfl_xor_sync(0xFFFFFFFFu, top[3], off);
        ins4(top, o0); ins4(top, o1); ins4(top, o2); ins4(top, o3);
    }
}

// ---------------- kernels ----------------
// one warp per row; float4 loads (80 floats = 20 float4). Also zeroes d_out.
__global__ __launch_bounds__(256) void k_labelid(const float* __restrict__ labels,
                                                 float* __restrict__ out,
                                                 int out_size) {
    int warp = (blockIdx.x * blockDim.x + threadIdx.x) >> 5;
    int lane = threadIdx.x & 31;
    if (blockIdx.x == 0 && threadIdx.x < out_size) out[threadIdx.x] = 0.0f;
    if (warp >= BN) return;
    const float4* row = (const float4*)(labels + (size_t)warp * CN);
    unsigned best = 0;
    if (lane < CN / 4) {
        float4 v = row[lane];
        unsigned j = (unsigned)lane * 4u;
        if (v.x > 0.5f) best = j;
        if (v.y > 0.5f) best = j + 1;
        if (v.z > 0.5f) best = j + 2;
        if (v.w > 0.5f) best = j + 3;
    }
    best = __reduce_max_sync(0xFFFFFFFFu, best);
    if (lane == 0) g_lid8[warp] = (unsigned char)best;
}

// PHASE 1, VALUE-ONLY. grid (4096, 4), block 64. Virtual thread
// vt = by*64 + tid owns j in [16*vt, 16*vt+16). Per vt, per key:
//   best = max over s of ((bits>>9)+1) * valid   (0 if none valid)
// unroll 8 x 2 keys = 16 independent chains this round (probe).
// No position tracking; no smem; no barriers.
__global__ __launch_bounds__(64) void k_select(uint32_t a0, uint32_t a1,
                                               uint32_t b0, uint32_t b1) {
    const int row = blockIdx.x;
    const int vt = blockIdx.y * 64 + threadIdx.x;   // 0..255
    const uint32_t ksA2 = a0 ^ a1 ^ 0x1BD11BDAu;
    const uint32_t ksB2 = b0 ^ b1 ^ 0x1BD11BDAu;

    const uint32_t mylid = (uint32_t)g_lid8[row];
    const uint32_t rep = mylid * 0x01010101u;
    const uint4 l4 = reinterpret_cast<const uint4*>(g_lid8)[vt];
    uint32_t vw[4];
    vw[0] = __vcmpne4(l4.x, rep) & 0x01010101u;
    vw[1] = __vcmpne4(l4.y, rep) & 0x01010101u;
    vw[2] = __vcmpne4(l4.z, rep) & 0x01010101u;
    vw[3] = __vcmpne4(l4.w, rep) & 0x01010101u;

    const uint32_t cbase = (uint32_t)row * (uint32_t)BN + (uint32_t)vt * 16u;

    uint32_t bestA = 0u, bestB = 0u;
    #pragma unroll 8
    for (int s = 0; s < 16; s++) {
        uint32_t bitsA = tf_bits(a0, a1, ksA2, cbase + (uint32_t)s);
        uint32_t bitsB = tf_bits(b0, b1, ksB2, cbase + (uint32_t)s);
        uint32_t v01 = __byte_perm(vw[s >> 2], 0u, 0x4440u | (unsigned)(s & 3));
        uint32_t cA = (bitsA >> 9) * v01 + v01;   // ((bits>>9)+1)*valid
        uint32_t cB = (bitsB >> 9) * v01 + v01;
        bestA = max(bestA, cA);
        bestB = max(bestB, cB);
    }

    g_best32[0][row][vt] = bestA;
    g_best32[1][row][vt] = bestB;
}

__device__ __forceinline__ float warp_sum(float s) {
    for (int off = 16; off > 0; off >>= 1)
        s += __shfl_xor_sync(0xFFFFFFFFu, s, off);
    return s;
}

__device__ __forceinline__ float dist4(float4 a, float4 b) {
    float dx = a.x - b.x, dy = a.y - b.y, dz = a.z - b.z, dw = a.w - b.w;
    float s = dx * dx + dy * dy + dz * dz + dw * dw;
    s = warp_sum(s);
    return sqrtf(fmaxf(s, 0.0f));
}

// FUSED merge + rescan + loss. grid 1024, block 256 = 8 warps;
// warp w -> pair g = blockIdx.x*8+w -> (row = g>>1, dir = g&1).
// Step 1: warp top-4 owner vthreads by (value<<8)|(255-t)  [u32].
// Step 2: exact rescan of the 4 owners (64 evals, 2/lane) with u64 packing
//         ((v+1)<<12)|(4095-j), ties -> lower j. All lanes converge.
// Step 3: distances for this (row,dir): pos + 4 negatives, hinge, reduce.
__global__ __launch_bounds__(256) void k_mergeloss(const float* __restrict__ img,
                                                   const float* __restrict__ txt,
                                                   float* __restrict__ out,
                                                   uint32_t a0, uint32_t a1,
                                                   uint32_t b0, uint32_t b1) {
    const int w = threadIdx.x >> 5;
    const int lane = threadIdx.x & 31;
    const int g = blockIdx.x * 8 + w;
    const int row = g >> 1;
    const int dir = g & 1;

    const uint32_t kk0 = dir ? b0 : a0;
    const uint32_t kk1 = dir ? b1 : a1;
    const uint32_t kks2 = kk0 ^ kk1 ^ 0x1BD11BDAu;
    const uint32_t mylid = (uint32_t)g_lid8[row];

    // step 1: top-4 owner vthreads (value, lower-t wins ties)
    uint32_t top[4] = {0u, 0u, 0u, 0u};
    #pragma unroll
    for (int k = 0; k < 8; k++) {
        int t = lane + 32 * k;
        uint32_t v = g_best32[dir][row][t];   // (bits>>9)+1, or 0
        if (v) ins4u(top, (v << 8) | (uint32_t)(255 - t));
    }
    warp_merge4u(top);   // all lanes: same 4 packed owners

    // step 2: exact rescan, 2 evals per lane
    unsigned long long fin[4] = {0ull, 0ull, 0ull, 0ull};
    #pragma unroll
    for (int k = 0; k < 2; k++) {
        int p = lane + 32 * k;          // 0..63
        int c = p >> 4;                 // candidate 0..3
        int s = p & 15;                 // element within owner thread
        uint32_t tc = top[c];
        if (tc != 0u) {
            int to = 255 - (int)(tc & 0xFFu);   // owner vthread
            int j = to * 16 + s;
            if ((uint32_t)g_lid8[j] != mylid) {
                uint32_t bits = tf_bits(kk0, kk1, kks2,
                                        (uint32_t)row * (uint32_t)BN + (uint32_t)j);
                unsigned long long pv =
                    (((unsigned long long)((bits >> 9) + 1u)) << 12) |
                    (unsigned long long)(BN - 1 - j);
                ins4(fin, pv);
            }
        }
    }
    warp_merge4(fin);   // all lanes: final top-4 (exact)

    // step 3: distances
    const float4* img4 = (const float4*)img;
    const float4* txt4 = (const float4*)txt;

    float4 ai = img4[row * 32 + lane];
    float4 ti = txt4[row * 32 + lane];
    float pos = dist4(ai, ti);

    const float4* nsrc = dir ? img4 : txt4;
    float4 anc = dir ? ti : ai;

    float acc = 0.0f;
    #pragma unroll
    for (int k = 0; k < ERRN; k++) {
        int j = BN - 1 - (int)(fin[k] & 0xFFFull);   // warp-uniform
        float4 bj = nsrc[j * 32 + lane];
        float neg = dist4(anc, bj);
        acc += fmaxf(pos - neg + 1.0f, 0.0f);
    }

    __shared__ float ssum[8];
    if (lane == 0) ssum[w] = acc;
    __syncthreads();
    if (threadIdx.x == 0) {
        float t = 0.0f;
        #pragma unroll
        for (int k = 0; k < 8; k++) t += ssum[k];
        atomicAdd(out, t * (1.0f / (float)(BN * ERRN)));
    }
}

// ---------------- launch ----------------
extern "C" void kernel_launch(void* const* d_in, const int* in_sizes, int n_in,
                              void* d_out, int out_size) {
    const float* img    = (const float*)d_in[0];
    const float* txt    = (const float*)d_in[1];
    const float* labels = (const float*)d_in[2];
    float* out = (float*)d_out;

    // jax.random.key(42) -> (0,42); partitionable foldlike split:
    // key_i = threefry((0,42), (0, i)).
    uint32_t a0, a1, b0, b1;
    threefry2x32(0u, 42u, 0u, 0u, a0, a1);  // ks1 (image->text scores)
    threefry2x32(0u, 42u, 0u, 1u, b0, b1);  // ks2 (text->image scores)

    k_labelid<<<512, 256>>>(labels, out, out_size);
    dim3 gsel(BN, 4);
    k_select<<<gsel, 64>>>(a0, a1, b0, b1);
    k_mergeloss<<<BN / 4, 256>>>(img, txt, out, a0, a1, b0, b1);
}

// round 15
// speedup vs baseline: 1.2076x; 1.0006x over previous
#include <cuda_runtime.h>
#include <cstdint>

#define BN 4096
#define CN 80
#define ERRN 4

// ---------------- scratch (static device arrays; no allocation) ----------------
__device__ __align__(16) unsigned char g_lid8[BN];
__device__ uint32_t g_best32[2][BN][256];   // per-virtual-thread best VALUES (8 MB)

// ---------------- threefry2x32 (exact JAX semantics) ----------------
__host__ __device__ __forceinline__ uint32_t tf_rotl(uint32_t v, int r) {
    return (v << r) | (v >> (32 - r));
}

// full version (host key derivation)
__host__ __device__ __forceinline__ void threefry2x32(uint32_t k0, uint32_t k1,
                                                      uint32_t c0, uint32_t c1,
                                                      uint32_t& o0, uint32_t& o1) {
    uint32_t ks0 = k0, ks1 = k1, ks2 = k0 ^ k1 ^ 0x1BD11BDAu;
    uint32_t x0 = c0 + ks0;
    uint32_t x1 = c1 + ks1;
#define TF_RND(r) { x0 += x1; x1 = tf_rotl(x1, r); x1 ^= x0; }
    TF_RND(13) TF_RND(15) TF_RND(26) TF_RND(6)
    x0 += ks1; x1 += ks2 + 1u;
    TF_RND(17) TF_RND(29) TF_RND(16) TF_RND(24)
    x0 += ks2; x1 += ks0 + 2u;
    TF_RND(13) TF_RND(15) TF_RND(26) TF_RND(6)
    x0 += ks0; x1 += ks1 + 3u;
    TF_RND(17) TF_RND(29) TF_RND(16) TF_RND(24)
    x0 += ks1; x1 += ks2 + 4u;
    TF_RND(13) TF_RND(15) TF_RND(26) TF_RND(6)
    x0 += ks2; x1 += ks0 + 5u;
#undef TF_RND
    o0 = x0; o1 = x1;
}

// Hot path: x0^x1 of threefry((k0,k1),(0,c1)). SHF/LOP3 form — verified
// best instruction selection (forced IMAD.WIDE regressed, R13).
__device__ __forceinline__ uint32_t tf_bits(uint32_t k0, uint32_t k1,
                                            uint32_t ks2, uint32_t c1) {
    uint32_t x0 = k0;
    uint32_t x1 = c1 + k1;
#define RND(r) { x0 += x1; x1 = __funnelshift_l(x1, x1, (r)) ^ x0; }
#define GRP_A RND(13) RND(15) RND(26) RND(6)
#define GRP_B RND(17) RND(29) RND(16) RND(24)
    GRP_A
    x0 += k1;  x1 += ks2 + 1u;
    GRP_B
    x0 += ks2; x1 += k0 + 2u;
    GRP_A
    x0 += k0;  x1 += k1 + 3u;
    GRP_B
    x0 += k1;  x1 += ks2 + 4u;
    GRP_A
    x0 += ks2; x1 += k0 + 5u;
#undef GRP_A
#undef GRP_B
#undef RND
    return x0 ^ x1;
}

// ---------------- top-4 helpers ----------------
__device__ __forceinline__ void ins4u(uint32_t* t, uint32_t c) {
    if (c > t[0])      { t[3] = t[2]; t[2] = t[1]; t[1] = t[0]; t[0] = c; }
    else if (c > t[1]) { t[3] = t[2]; t[2] = t[1]; t[1] = c; }
    else if (c > t[2]) { t[3] = t[2]; t[2] = c; }
    else if (c > t[3]) { t[3] = c; }
}

__device__ __forceinline__ void warp_merge4u(uint32_t* top) {
    for (int off = 16; off > 0; off >>= 1) {
        uint32_t o0 = __shfl_xor_sync(0xFFFFFFFFu, top[0], off);
        uint32_t o1 = __shfl_xor_sync(0xFFFFFFFFu, top[1], off);
        uint32_t o2 = __shfl_xor_sync(0xFFFFFFFFu, top[2], off);
        uint32_t o3 = __shfl_xor_sync(0xFFFFFFFFu, top[3], off);
        ins4u(top, o0); ins4u(top, o1); ins4u(top, o2); ins4u(top, o3);
    }
}

__device__ __forceinline__ void ins4(unsigned long long* t, unsigned long long c) {
    if (c > t[0])      { t[3] = t[2]; t[2] = t[1]; t[1] = t[0]; t[0] = c; }
    else if (c > t[1]) { t[3] = t[2]; t[2] = t[1]; t[1] = c; }
    else if (c > t[2]) { t[3] = t[2]; t[2] = c; }
    else if (c > t[3]) { t[3] = c; }
}

__device__ __forceinline__ void warp_merge4(unsigned long long* top) {
    for (int off = 16; off > 0; off >>= 1) {
        unsigned long long o0 = __shfl_xor_sync(0xFFFFFFFFu, top[0], off);
        unsigned long long o1 = __shfl_xor_sync(0xFFFFFFFFu, top[1], off);
        unsigned long long o2 = __shfl_xor_sync(0xFFFFFFFFu, top[2], off);
        unsigned long long o3 = __shfl_xor_sync(0xFFFFFFFFu, top[3], off);
        ins4(top, o0); ins4(top, o1); ins4(top, o2); ins4(top, o3);
    }
}

// ---------------- kernels ----------------
// MLP-structured: grid 64, block 256 = 8 warps; each warp owns 8 rows and
// issues all 8 float4 loads back-to-back (independent) before reducing, so
// DRAM/TLB latency is overlapped (MLP=8/lane). Also zeroes d_out.
__global__ __launch_bounds__(256) void k_labelid(const float* __restrict__ labels,
                                                 float* __restrict__ out,
                                                 int out_size) {
    const int w = (blockIdx.x * blockDim.x + threadIdx.x) >> 5;
    const int lane = threadIdx.x & 31;
    if (blockIdx.x == 0 && threadIdx.x < out_size) out[threadIdx.x] = 0.0f;

    const int row0 = w * 8;
    float4 v[8];
    const bool act = lane < CN / 4;
    #pragma unroll
    for (int k = 0; k < 8; k++) {
        const float4* row = (const float4*)(labels + (size_t)(row0 + k) * CN);
        v[k] = act ? row[lane] : make_float4(0.f, 0.f, 0.f, 0.f);
    }
    #pragma unroll
    for (int k = 0; k < 8; k++) {
        unsigned best = 0;
        unsigned j = (unsigned)lane * 4u;
        if (v[k].x > 0.5f) best = j;
        if (v[k].y > 0.5f) best = j + 1;
        if (v[k].z > 0.5f) best = j + 2;
        if (v[k].w > 0.5f) best = j + 3;
        best = __reduce_max_sync(0xFFFFFFFFu, best);
        if (lane == 0) g_lid8[row0 + k] = (unsigned char)best;
    }
}

// PHASE 1, VALUE-ONLY. grid (4096, 4), block 64. Virtual thread
// vt = by*64 + tid owns j in [16*vt, 16*vt+16). Per vt, per key:
//   best = max over s of ((bits>>9)+1) * valid   (0 if none valid)
// unroll 4 x 2 keys = 8 independent chains (best-measured config).
// No position tracking; no smem; no barriers.
__global__ __launch_bounds__(64) void k_select(uint32_t a0, uint32_t a1,
                                               uint32_t b0, uint32_t b1) {
    const int row = blockIdx.x;
    const int vt = blockIdx.y * 64 + threadIdx.x;   // 0..255
    const uint32_t ksA2 = a0 ^ a1 ^ 0x1BD11BDAu;
    const uint32_t ksB2 = b0 ^ b1 ^ 0x1BD11BDAu;

    const uint32_t mylid = (uint32_t)g_lid8[row];
    const uint32_t rep = mylid * 0x01010101u;
    const uint4 l4 = reinterpret_cast<const uint4*>(g_lid8)[vt];
    uint32_t vw[4];
    vw[0] = __vcmpne4(l4.x, rep) & 0x01010101u;
    vw[1] = __vcmpne4(l4.y, rep) & 0x01010101u;
    vw[2] = __vcmpne4(l4.z, rep) & 0x01010101u;
    vw[3] = __vcmpne4(l4.w, rep) & 0x01010101u;

    const uint32_t cbase = (uint32_t)row * (uint32_t)BN + (uint32_t)vt * 16u;

    uint32_t bestA = 0u, bestB = 0u;
    #pragma unroll 4
    for (int s = 0; s < 16; s++) {
        uint32_t bitsA = tf_bits(a0, a1, ksA2, cbase + (uint32_t)s);
        uint32_t bitsB = tf_bits(b0, b1, ksB2, cbase + (uint32_t)s);
        uint32_t v01 = __byte_perm(vw[s >> 2], 0u, 0x4440u | (unsigned)(s & 3));
        uint32_t cA = (bitsA >> 9) * v01 + v01;   // ((bits>>9)+1)*valid
        uint32_t cB = (bitsB >> 9) * v01 + v01;
        bestA = max(bestA, cA);
        bestB = max(bestB, cB);
    }

    g_best32[0][row][vt] = bestA;
    g_best32[1][row][vt] = bestB;
}

__device__ __forceinline__ float warp_sum(float s) {
    for (int off = 16; off > 0; off >>= 1)
        s += __shfl_xor_sync(0xFFFFFFFFu, s, off);
    return s;
}

__device__ __forceinline__ float dist4(float4 a, float4 b) {
    float dx = a.x - b.x, dy = a.y - b.y, dz = a.z - b.z, dw = a.w - b.w;
    float s = dx * dx + dy * dy + dz * dz + dw * dw;
    s = warp_sum(s);
    return sqrtf(fmaxf(s, 0.0f));
}

// FUSED merge + rescan + loss. grid 1024, block 256 = 8 warps;
// warp w -> pair g = blockIdx.x*8+w -> (row = g>>1, dir = g&1).
// Step 1: warp top-4 owner vthreads by (value<<8)|(255-t)  [u32].
// Step 2: exact rescan of the 4 owners (64 evals, 2/lane) with u64 packing
//         ((v+1)<<12)|(4095-j), ties -> lower j. All lanes converge.
// Step 3: distances for this (row,dir): pos + 4 negatives, hinge, reduce.
__global__ __launch_bounds__(256) void k_mergeloss(const float* __restrict__ img,
                                                   const float* __restrict__ txt,
                                                   float* __restrict__ out,
                                                   uint32_t a0, uint32_t a1,
                                                   uint32_t b0, uint32_t b1) {
    const int w = threadIdx.x >> 5;
    const int lane = threadIdx.x & 31;
    const int g = blockIdx.x * 8 + w;
    const int row = g >> 1;
    const int dir = g & 1;

    const uint32_t kk0 = dir ? b0 : a0;
    const uint32_t kk1 = dir ? b1 : a1;
    const uint32_t kks2 = kk0 ^ kk1 ^ 0x1BD11BDAu;
    const uint32_t mylid = (uint32_t)g_lid8[row];

    // step 1: top-4 owner vthreads (value, lower-t wins ties)
    uint32_t top[4] = {0u, 0u, 0u, 0u};
    #pragma unroll
    for (int k = 0; k < 8; k++) {
        int t = lane + 32 * k;
        uint32_t v = g_best32[dir][row][t];   // (bits>>9)+1, or 0
        if (v) ins4u(top, (v << 8) | (uint32_t)(255 - t));
    }
    warp_merge4u(top);   // all lanes: same 4 packed owners

    // step 2: exact rescan, 2 evals per lane
    unsigned long long fin[4] = {0ull, 0ull, 0ull, 0ull};
    #pragma unroll
    for (int k = 0; k < 2; k++) {
        int p = lane + 32 * k;          // 0..63
        int c = p >> 4;                 // candidate 0..3
        int s = p & 15;                 // element within owner thread
        uint32_t tc = top[c];
        if (tc != 0u) {
            int to = 255 - (int)(tc & 0xFFu);   // owner vthread
            int j = to * 16 + s;
            if ((uint32_t)g_lid8[j] != mylid) {
                uint32_t bits = tf_bits(kk0, kk1, kks2,
                                        (uint32_t)row * (uint32_t)BN + (uint32_t)j);
                unsigned long long pv =
                    (((unsigned long long)((bits >> 9) + 1u)) << 12) |
                    (unsigned long long)(BN - 1 - j);
                ins4(fin, pv);
            }
        }
    }
    warp_merge4(fin);   // all lanes: final top-4 (exact)

    // step 3: distances
    const float4* img4 = (const float4*)img;
    const float4* txt4 = (const float4*)txt;

    float4 ai = img4[row * 32 + lane];
    float4 ti = txt4[row * 32 + lane];
    float pos = dist4(ai, ti);

    const float4* nsrc = dir ? img4 : txt4;
    float4 anc = dir ? ti : ai;

    float acc = 0.0f;
    #pragma unroll
    for (int k = 0; k < ERRN; k++) {
        int j = BN - 1 - (int)(fin[k] & 0xFFFull);   // warp-uniform
        float4 bj = nsrc[j * 32 + lane];
        float neg = dist4(anc, bj);
        acc += fmaxf(pos - neg + 1.0f, 0.0f);
    }

    __shared__ float ssum[8];
    if (lane == 0) ssum[w] = acc;
    __syncthreads();
    if (threadIdx.x == 0) {
        float t = 0.0f;
        #pragma unroll
        for (int k = 0; k < 8; k++) t += ssum[k];
        atomicAdd(out, t * (1.0f / (float)(BN * ERRN)));
    }
}

// ---------------- launch ----------------
extern "C" void kernel_launch(void* const* d_in, const int* in_sizes, int n_in,
                              void* d_out, int out_size) {
    const float* img    = (const float*)d_in[0];
    const float* txt    = (const float*)d_in[1];
    const float* labels = (const float*)d_in[2];
    float* out = (float*)d_out;

    // jax.random.key(42) -> (0,42); partitionable foldlike split:
    // key_i = threefry((0,42), (0, i)).
    uint32_t a0, a1, b0, b1;
    threefry2x32(0u, 42u, 0u, 0u, a0, a1);  // ks1 (image->text scores)
    threefry2x32(0u, 42u, 0u, 1u, b0, b1);  // ks2 (text->image scores)

    k_labelid<<<64, 256>>>(labels, out, out_size);
    dim3 gsel(BN, 4);
    k_select<<<gsel, 64>>>(a0, a1, b0, b1);
    k_mergeloss<<<BN / 4, 256>>>(img, txt, out, a0, a1, b0, b1);
}